// round 5
// baseline (speedup 1.0000x reference)
#include <cuda_runtime.h>
#include <cstdint>

#define B_   64
#define N_   128
#define F_   128
#define R_   64
#define H_   256
#define L_   3
#define ROWS (B_*N_)

__device__ float g_v[F_];

__device__ __forceinline__ uint32_t f2tf(float x) {
    uint32_t r; asm("cvt.rna.tf32.f32 %0, %1;" : "=r"(r) : "f"(x)); return r;
}
__device__ __forceinline__ float tanh_fast(float x) {
    float r; asm("tanh.approx.f32 %0, %1;" : "=f"(r) : "f"(x)); return r;
}
__device__ __forceinline__ void mma8(float* d, uint32_t a0, uint32_t a1, uint32_t a2, uint32_t a3,
                                     uint32_t b0, uint32_t b1) {
    asm volatile(
        "mma.sync.aligned.m16n8k8.row.col.f32.tf32.tf32.f32 "
        "{%0,%1,%2,%3},{%4,%5,%6,%7},{%8,%9},{%0,%1,%2,%3};"
        : "+f"(d[0]), "+f"(d[1]), "+f"(d[2]), "+f"(d[3])
        : "r"(a0), "r"(a1), "r"(a2), "r"(a3), "r"(b0), "r"(b1));
}
__device__ __forceinline__ uint32_t ldw(const float* p) { return *(const uint32_t*)p; }

// Stage [RT x KC] fp32 (src row stride SS) -> smem row-major stride DS, tf32-rounded.
template<int RT, int KC, int SS, int DS>
__device__ __forceinline__ void stage(float* dst, const float* __restrict__ src, int tid) {
    constexpr int K4 = KC / 4;
    #pragma unroll
    for (int idx = tid; idx < RT * K4; idx += 256) {
        int row = idx / K4;
        int c4 = (idx - row * K4) * 4;
        float4 v = *(const float4*)(src + (size_t)row * SS + c4);
        uint4 o;
        o.x = f2tf(v.x); o.y = f2tf(v.y); o.z = f2tf(v.z); o.w = f2tf(v.w);
        *(uint4*)(dst + row * DS + c4) = o;
    }
}

// ---------------- Kernel 1: fold head, write g_v, init out[b] = cs ----------------
__global__ void fold_head_kernel(const float* __restrict__ fc0_w, const float* __restrict__ fc0_b,
                                 const float* __restrict__ out_w, const float* __restrict__ out_b,
                                 float* __restrict__ out) {
    int f = threadIdx.x;   // 128
    float a = 0.f;
    #pragma unroll 8
    for (int c = 0; c < 256; c++) a += out_w[c] * fc0_w[c * F_ + f];
    g_v[f] = a;
    __shared__ float cs;
    if (f == 0) {
        float s = out_b[0];
        for (int c = 0; c < 256; c++) s += out_w[c] * fc0_b[c];
        cs = s;
    }
    __syncthreads();
    if (f < B_) out[f] = cs;
}

// ---------------- Kernel 2: fully fused reduce + 3 layers + pool ----------------
// 128 CTAs x 64 rows, 256 threads. smem word offsets:
enum {
    OXS  = 0,                    // Xs  [64][132]
    ODS  = OXS + 8448,           // Ds  [64][68]
    OPB  = ODS + 4352,           // Pb  [64][68]
    OCF0 = OPB + 4352,           // CF0 [64][132]
    OCF1 = OCF0 + 8448,          // CF1 [64][132]
    ODF0 = OCF1 + 8448,          // DF0 [64][68]
    ODF1 = ODF0 + 4352,          // DF1 [64][68]
    OFC  = ODF1 + 4352,          // FCb [128][68]
    OBC  = OFC + 8704,           // bcf [256]
    OBD  = OBC + 256,            // 128*bdf [256]
    OVV  = OBD + 256,            // v [128]
    ORD  = OVV + 128,            // reduce [256]
    TOTW = ORD + 256             // 52352 words = 209408 B
};
#define SMEMB (TOTW * 4)

__global__ __launch_bounds__(256, 1)
void dtnn_fused_kernel(const float* __restrict__ x, const float* __restrict__ dist,
                       const float* __restrict__ Wcf_w, const float* __restrict__ Wcf_b,
                       const float* __restrict__ Wdf_w, const float* __restrict__ Wdf_b,
                       const float* __restrict__ Wfc_w,
                       float* __restrict__ out) {
    extern __shared__ float sm[];
    float* Xs = sm + OXS; float* Ds = sm + ODS; float* Pb = sm + OPB;
    float* CFb[2] = { sm + OCF0, sm + OCF1 };
    float* DFb[2] = { sm + ODF0, sm + ODF1 };
    float* FCb = sm + OFC;
    float* bc = sm + OBC; float* bd = sm + OBD;
    float* vv = sm + OVV; float* rd = sm + ORD;

    int tid = threadIdx.x, lane = tid & 31, w = tid >> 5;
    int g = lane >> 2, t = lane & 3;
    int wm = w & 1, wn = w >> 1;          // warp grid: 2 (M) x 4 (N)
    int rows0 = blockIdx.x * 64;

    // stage x tile + layer-0 chunk-0 weights + biases + v
    stage<64, 128, 128, 132>(Xs, x + (size_t)rows0 * 128, tid);
    stage<64, 128, 128, 132>(CFb[0], Wcf_w, tid);
    stage<64, 64, 64, 68>(DFb[0], Wdf_w, tid);
    bc[tid] = Wcf_b[tid];
    bd[tid] = 128.f * Wdf_b[tid];
    if (tid < 128) vv[tid] = g_v[tid];

    // in-CTA distance reduction: Ds[row][r] = sum_j dist[row][j][r] (tf32)
    {
        int row = tid >> 2, q = tid & 3;
        const float* p = dist + ((size_t)(rows0 + row)) * (N_ * R_) + q * 16;
        float4 a0 = {0,0,0,0}, a1 = {0,0,0,0}, a2 = {0,0,0,0}, a3 = {0,0,0,0};
        #pragma unroll 4
        for (int j = 0; j < 128; j++) {
            const float4* q4 = (const float4*)(p + j * 64);
            float4 v0 = q4[0], v1 = q4[1], v2 = q4[2], v3 = q4[3];
            a0.x += v0.x; a0.y += v0.y; a0.z += v0.z; a0.w += v0.w;
            a1.x += v1.x; a1.y += v1.y; a1.z += v1.z; a1.w += v1.w;
            a2.x += v2.x; a2.y += v2.y; a2.z += v2.z; a2.w += v2.w;
            a3.x += v3.x; a3.y += v3.y; a3.z += v3.z; a3.w += v3.w;
        }
        uint4 o;
        float* dp = Ds + row * 68 + q * 16;
        o.x = f2tf(a0.x); o.y = f2tf(a0.y); o.z = f2tf(a0.z); o.w = f2tf(a0.w); *(uint4*)(dp + 0)  = o;
        o.x = f2tf(a1.x); o.y = f2tf(a1.y); o.z = f2tf(a1.z); o.w = f2tf(a1.w); *(uint4*)(dp + 4)  = o;
        o.x = f2tf(a2.x); o.y = f2tf(a2.y); o.z = f2tf(a2.z); o.w = f2tf(a2.w); *(uint4*)(dp + 8)  = o;
        o.x = f2tf(a3.x); o.y = f2tf(a3.y); o.z = f2tf(a3.z); o.w = f2tf(a3.w); *(uint4*)(dp + 12) = o;
    }

    float hacc[2][4][4] = {};
    float pool = 0.f;

    for (int i = 0; i < 12; i++) {
        int l = i >> 2, c = i & 3, buf = i & 1;
        const float* wfc = Wfc_w + (size_t)l * F_ * H_;

        __syncthreads();   // sync A: CF/DF[i], FCb free, Pb free, Xs/bc/bd ready

        // prefetch: FC chunk i, CF/DF chunk i+1 (hidden under cf/df mma)
        stage<128, 64, 256, 68>(FCb, wfc + c * 64, tid);
        if (i < 11) {
            int ln = (i + 1) >> 2, cn = (i + 1) & 3;
            stage<64, 128, 128, 132>(CFb[buf ^ 1], Wcf_w + (size_t)ln * 32768 + cn * 8192, tid);
            stage<64, 64, 64, 68>(DFb[buf ^ 1], Wdf_w + (size_t)ln * 16384 + cn * 4096, tid);
        }

        float* CF = CFb[buf];
        float* DF = DFb[buf];
        float cf[2][2][4] = {}, df[2][2][4] = {};
        // cf: Xs[64x128] @ CF^T -> 64x64 (warp tile 32x16)
        #pragma unroll
        for (int ks = 0; ks < 16; ks++) {
            int k0 = ks * 8;
            uint32_t A[2][4];
            #pragma unroll
            for (int mt = 0; mt < 2; mt++) {
                const float* ba = Xs + (wm * 32 + mt * 16 + g) * 132 + k0 + t;
                A[mt][0] = ldw(ba); A[mt][1] = ldw(ba + 8 * 132);
                A[mt][2] = ldw(ba + 4); A[mt][3] = ldw(ba + 8 * 132 + 4);
            }
            #pragma unroll
            for (int nt = 0; nt < 2; nt++) {
                const float* bb = CF + (wn * 16 + nt * 8 + g) * 132 + k0 + t;
                uint32_t b0 = ldw(bb), b1 = ldw(bb + 4);
                mma8(cf[0][nt], A[0][0], A[0][1], A[0][2], A[0][3], b0, b1);
                mma8(cf[1][nt], A[1][0], A[1][1], A[1][2], A[1][3], b0, b1);
            }
        }
        // df: Ds[64x64] @ DF^T -> 64x64
        #pragma unroll
        for (int ks = 0; ks < 8; ks++) {
            int k0 = ks * 8;
            uint32_t A[2][4];
            #pragma unroll
            for (int mt = 0; mt < 2; mt++) {
                const float* ba = Ds + (wm * 32 + mt * 16 + g) * 68 + k0 + t;
                A[mt][0] = ldw(ba); A[mt][1] = ldw(ba + 8 * 68);
                A[mt][2] = ldw(ba + 4); A[mt][3] = ldw(ba + 8 * 68 + 4);
            }
            #pragma unroll
            for (int nt = 0; nt < 2; nt++) {
                const float* bb = DF + (wn * 16 + nt * 8 + g) * 68 + k0 + t;
                uint32_t b0 = ldw(bb), b1 = ldw(bb + 4);
                mma8(df[0][nt], A[0][0], A[0][1], A[0][2], A[0][3], b0, b1);
                mma8(df[1][nt], A[1][0], A[1][1], A[1][2], A[1][3], b0, b1);
            }
        }
        // P = (cf+bc)*(df+128*bd) -> Pb
        int hc = c * 64;
        #pragma unroll
        for (int mt = 0; mt < 2; mt++)
        #pragma unroll
        for (int nt = 0; nt < 2; nt++) {
            int col = wn * 16 + nt * 8 + 2 * t;
            int row = wm * 32 + mt * 16 + g;
            float b0c = bc[hc + col], b1c = bc[hc + col + 1];
            float b0d = bd[hc + col], b1d = bd[hc + col + 1];
            float* f4 = cf[mt][nt];
            float* d4 = df[mt][nt];
            uint2 p01, p23;
            p01.x = f2tf((f4[0] + b0c) * (d4[0] + b0d));
            p01.y = f2tf((f4[1] + b1c) * (d4[1] + b1d));
            p23.x = f2tf((f4[2] + b0c) * (d4[2] + b0d));
            p23.y = f2tf((f4[3] + b1c) * (d4[3] + b1d));
            *(uint2*)(Pb + row * 68 + col) = p01;
            *(uint2*)(Pb + (row + 8) * 68 + col) = p23;
        }

        __syncthreads();   // sync B: Pb + FCb ready

        // fc: Pb[64x64] @ FCb^T accumulate -> hacc (warp 32x32)
        #pragma unroll
        for (int ks = 0; ks < 8; ks++) {
            int k0 = ks * 8;
            uint32_t A[2][4];
            #pragma unroll
            for (int mt = 0; mt < 2; mt++) {
                const float* ba = Pb + (wm * 32 + mt * 16 + g) * 68 + k0 + t;
                A[mt][0] = ldw(ba); A[mt][1] = ldw(ba + 8 * 68);
                A[mt][2] = ldw(ba + 4); A[mt][3] = ldw(ba + 8 * 68 + 4);
            }
            #pragma unroll
            for (int nt = 0; nt < 4; nt++) {
                const float* bb = FCb + (wn * 32 + nt * 8 + g) * 68 + k0 + t;
                uint32_t b0 = ldw(bb), b1 = ldw(bb + 4);
                mma8(hacc[0][nt], A[0][0], A[0][1], A[0][2], A[0][3], b0, b1);
                mma8(hacc[1][nt], A[1][0], A[1][1], A[1][2], A[1][3], b0, b1);
            }
        }

        if (c == 3) {
            if (l < 2) {
                // x = h + tanh(h) -> Xs; load next layer biases
                #pragma unroll
                for (int mt = 0; mt < 2; mt++)
                #pragma unroll
                for (int nt = 0; nt < 4; nt++) {
                    int row = wm * 32 + mt * 16 + g;
                    int col = wn * 32 + nt * 8 + 2 * t;
                    float* h4 = hacc[mt][nt];
                    uint2 x01, x23;
                    x01.x = f2tf(h4[0] + tanh_fast(h4[0]));
                    x01.y = f2tf(h4[1] + tanh_fast(h4[1]));
                    x23.x = f2tf(h4[2] + tanh_fast(h4[2]));
                    x23.y = f2tf(h4[3] + tanh_fast(h4[3]));
                    *(uint2*)(Xs + row * 132 + col) = x01;
                    *(uint2*)(Xs + (row + 8) * 132 + col) = x23;
                }
                bc[tid] = Wcf_b[(l + 1) * H_ + tid];
                bd[tid] = 128.f * Wdf_b[(l + 1) * H_ + tid];
                #pragma unroll
                for (int mt = 0; mt < 2; mt++)
                #pragma unroll
                for (int nt = 0; nt < 4; nt++)
                #pragma unroll
                for (int e = 0; e < 4; e++) hacc[mt][nt][e] = 0.f;
            } else {
                #pragma unroll
                for (int mt = 0; mt < 2; mt++)
                #pragma unroll
                for (int nt = 0; nt < 4; nt++) {
                    int col = wn * 32 + nt * 8 + 2 * t;
                    float* h4 = hacc[mt][nt];
                    pool += (h4[0] + tanh_fast(h4[0])) * vv[col];
                    pool += (h4[1] + tanh_fast(h4[1])) * vv[col + 1];
                    pool += (h4[2] + tanh_fast(h4[2])) * vv[col];
                    pool += (h4[3] + tanh_fast(h4[3])) * vv[col + 1];
                }
                rd[tid] = pool;
                __syncthreads();
                for (int s = 128; s > 0; s >>= 1) {
                    if (tid < s) rd[tid] += rd[tid + s];
                    __syncthreads();
                }
                if (tid == 0) atomicAdd(out + (blockIdx.x >> 1), rd[0]);
            }
        }
    }
}

// ---------------- launch ----------------
extern "C" void kernel_launch(void* const* d_in, const int* in_sizes, int n_in,
                              void* d_out, int out_size) {
    const float* x     = (const float*)d_in[0];
    const float* dist  = (const float*)d_in[1];
    const float* Wcf_w = (const float*)d_in[2];
    const float* Wcf_b = (const float*)d_in[3];
    const float* Wdf_w = (const float*)d_in[4];
    const float* Wdf_b = (const float*)d_in[5];
    const float* Wfc_w = (const float*)d_in[6];
    const float* fc0_w = (const float*)d_in[7];
    const float* fc0_b = (const float*)d_in[8];
    const float* out_w = (const float*)d_in[9];
    const float* out_b = (const float*)d_in[10];
    float* out = (float*)d_out;

    cudaFuncSetAttribute(dtnn_fused_kernel,
                         cudaFuncAttributeMaxDynamicSharedMemorySize, SMEMB);

    fold_head_kernel<<<1, 128>>>(fc0_w, fc0_b, out_w, out_b, out);
    dtnn_fused_kernel<<<128, 256, SMEMB>>>(x, dist, Wcf_w, Wcf_b, Wdf_w, Wdf_b, Wfc_w, out);
}

// round 6
// speedup vs baseline: 1.0731x; 1.0731x over previous
#include <cuda_runtime.h>
#include <cstdint>

#define B_   64
#define N_   128
#define F_   128
#define R_   64
#define H_   256
#define L_   3
#define ROWS (B_*N_)

__device__ float g_dsum[ROWS * R_];
__device__ float g_v[F_];

__device__ __forceinline__ uint32_t f2tf(float x) {
    uint32_t r; asm("cvt.rna.tf32.f32 %0, %1;" : "=r"(r) : "f"(x)); return r;
}
__device__ __forceinline__ float tanh_fast(float x) {
    float r; asm("tanh.approx.f32 %0, %1;" : "=f"(r) : "f"(x)); return r;
}
__device__ __forceinline__ void mma8(float* d, uint32_t a0, uint32_t a1, uint32_t a2, uint32_t a3,
                                     uint32_t b0, uint32_t b1) {
    asm volatile(
        "mma.sync.aligned.m16n8k8.row.col.f32.tf32.tf32.f32 "
        "{%0,%1,%2,%3},{%4,%5,%6,%7},{%8,%9},{%0,%1,%2,%3};"
        : "+f"(d[0]), "+f"(d[1]), "+f"(d[2]), "+f"(d[3])
        : "r"(a0), "r"(a1), "r"(a2), "r"(a3), "r"(b0), "r"(b1));
}

// Packed staging: [RT x KC] fp32 (src row stride SS) -> smem tf32 rows of
// stride DS, with each k-octet permuted [0,4,1,5,2,6,3,7] so fragment pairs
// (k0+t, k0+t+4) are adjacent (enables LDS.64 fragment loads).
template<int RT, int KC, int SS, int DS>
__device__ __forceinline__ void stage_pk(float* dst, const float* __restrict__ src, int tid) {
    constexpr int K4 = KC / 4;
    uint32_t* du = (uint32_t*)dst;
    #pragma unroll
    for (int idx = tid; idx < RT * K4; idx += 256) {
        int row = idx / K4;
        int c4 = (idx - row * K4) * 4;
        float4 v = *(const float4*)(src + (size_t)row * SS + c4);
        int base = row * DS + (c4 & ~7) + ((c4 & 4) ? 1 : 0);
        du[base + 0] = f2tf(v.x);
        du[base + 2] = f2tf(v.y);
        du[base + 4] = f2tf(v.z);
        du[base + 6] = f2tf(v.w);
    }
}

// ---------------- Kernel A: d_sum row reduction (HBM-bound, 8192 blocks) ----------------
__global__ void reduce_dist_kernel(const float* __restrict__ dist) {
    int row = blockIdx.x;
    int tid = threadIdx.x;
    const float4* p = (const float4*)(dist + (size_t)row * (N_ * R_));
    float4 acc = make_float4(0.f, 0.f, 0.f, 0.f);
    #pragma unroll
    for (int t = 0; t < 8; t++) {
        float4 v = p[tid + t * 256];
        acc.x += v.x; acc.y += v.y; acc.z += v.z; acc.w += v.w;
    }
    __shared__ float4 s[256];
    s[tid] = acc;
    __syncthreads();
    if (tid < 16) {
        float4 a = s[tid];
        #pragma unroll
        for (int m = 1; m < 16; m++) {
            float4 b = s[tid + 16 * m];
            a.x += b.x; a.y += b.y; a.z += b.z; a.w += b.w;
        }
        ((float4*)(g_dsum + (size_t)row * R_))[tid] = a;
    }
}

// ---------------- Kernel C: fold head; init out[b] = cs ----------------
__global__ void fold_head_kernel(const float* __restrict__ fc0_w, const float* __restrict__ fc0_b,
                                 const float* __restrict__ out_w, const float* __restrict__ out_b,
                                 float* __restrict__ out) {
    int f = threadIdx.x;   // 128
    float a = 0.f;
    #pragma unroll 8
    for (int c = 0; c < 256; c++) a += out_w[c] * fc0_w[c * F_ + f];
    g_v[f] = a;
    __shared__ float cs;
    if (f == 0) {
        float s = out_b[0];
        for (int c = 0; c < 256; c++) s += out_w[c] * fc0_b[c];
        cs = s;
    }
    __syncthreads();
    if (f < B_) out[f] = cs;
}

// ---------------- Kernel B: mma.sync tf32 fused 3 layers + pooling ----------------
// 128 CTAs x 64 rows, 256 threads. Row strides: 136 (K=128), 72 (K=64).
enum {
    OXS  = 0,                    // Xs  [64][136]
    ODS  = OXS + 8704,           // Ds  [64][72]
    OPB  = ODS + 4608,           // Pb  [64][72]
    OCF0 = OPB + 4608,           // CF0 [64][136]
    OCF1 = OCF0 + 8704,          // CF1 [64][136]
    ODF0 = OCF1 + 8704,          // DF0 [64][72]
    ODF1 = ODF0 + 4608,          // DF1 [64][72]
    OFC  = ODF1 + 4608,          // FCb [128][72]
    OBC  = OFC + 9216,           // bcf [256]
    OBD  = OBC + 256,            // 128*bdf [256]
    OVV  = OBD + 256,            // v [128]
    ORD  = OVV + 128,            // reduce [256]
    TOTW = ORD + 256             // 54656 words = 218624 B
};
#define SMEMB (TOTW * 4)

__global__ __launch_bounds__(256, 1)
void dtnn_mma_kernel(const float* __restrict__ x,
                     const float* __restrict__ Wcf_w, const float* __restrict__ Wcf_b,
                     const float* __restrict__ Wdf_w, const float* __restrict__ Wdf_b,
                     const float* __restrict__ Wfc_w,
                     float* __restrict__ out) {
    extern __shared__ float sm[];
    float* Xs = sm + OXS; float* Ds = sm + ODS; float* Pb = sm + OPB;
    float* CFb[2] = { sm + OCF0, sm + OCF1 };
    float* DFb[2] = { sm + ODF0, sm + ODF1 };
    float* FCb = sm + OFC;
    float* bc = sm + OBC; float* bd = sm + OBD;
    float* vv = sm + OVV; float* rd = sm + ORD;
    uint32_t* Xu = (uint32_t*)Xs;
    uint32_t* Pu = (uint32_t*)Pb;

    int tid = threadIdx.x, lane = tid & 31, w = tid >> 5;
    int g = lane >> 2, t = lane & 3;
    int wm = w & 1, wn = w >> 1;          // warp grid: 2 (M) x 4 (N)
    int pe = (t < 2) ? 4 * t : 4 * t - 7; // packed pos of even col 2t; odd at +2
    int rows0 = blockIdx.x * 64;

    stage_pk<64, 128, 128, 136>(Xs, x + (size_t)rows0 * 128, tid);
    stage_pk<64, 64, 64, 72>(Ds, g_dsum + (size_t)rows0 * 64, tid);
    stage_pk<64, 128, 128, 136>(CFb[0], Wcf_w, tid);
    stage_pk<64, 64, 64, 72>(DFb[0], Wdf_w, tid);
    bc[tid] = Wcf_b[tid];
    bd[tid] = 128.f * Wdf_b[tid];
    if (tid < 128) vv[tid] = g_v[tid];

    float hacc[2][4][4] = {};
    float pool = 0.f;

    for (int i = 0; i < 12; i++) {
        int l = i >> 2, c = i & 3, buf = i & 1;
        const float* wfc = Wfc_w + (size_t)l * F_ * H_;

        __syncthreads();   // sync A

        // prefetch: FC chunk i; CF/DF chunk i+1 (hide under cf/df mma)
        stage_pk<128, 64, 256, 72>(FCb, wfc + c * 64, tid);
        if (i < 11) {
            int ln = (i + 1) >> 2, cn = (i + 1) & 3;
            stage_pk<64, 128, 128, 136>(CFb[buf ^ 1], Wcf_w + (size_t)ln * 32768 + cn * 8192, tid);
            stage_pk<64, 64, 64, 72>(DFb[buf ^ 1], Wdf_w + (size_t)ln * 16384 + cn * 4096, tid);
        }

        float* CF = CFb[buf];
        float* DF = DFb[buf];
        float cf[2][2][4] = {}, df[2][2][4] = {};
        // cf: Xs[64x128] @ CF^T (warp tile 32x16)
        #pragma unroll
        for (int ks = 0; ks < 16; ks++) {
            int k8 = ks * 8 + 2 * t;
            uint2 A0 = *(const uint2*)(Xs + (wm * 32 + g) * 136 + k8);
            uint2 A1 = *(const uint2*)(Xs + (wm * 32 + 8 + g) * 136 + k8);
            uint2 A2 = *(const uint2*)(Xs + (wm * 32 + 16 + g) * 136 + k8);
            uint2 A3 = *(const uint2*)(Xs + (wm * 32 + 24 + g) * 136 + k8);
            #pragma unroll
            for (int nt = 0; nt < 2; nt++) {
                uint2 Bv = *(const uint2*)(CF + (wn * 16 + nt * 8 + g) * 136 + k8);
                mma8(cf[0][nt], A0.x, A1.x, A0.y, A1.y, Bv.x, Bv.y);
                mma8(cf[1][nt], A2.x, A3.x, A2.y, A3.y, Bv.x, Bv.y);
            }
        }
        // df: Ds[64x64] @ DF^T
        #pragma unroll
        for (int ks = 0; ks < 8; ks++) {
            int k8 = ks * 8 + 2 * t;
            uint2 A0 = *(const uint2*)(Ds + (wm * 32 + g) * 72 + k8);
            uint2 A1 = *(const uint2*)(Ds + (wm * 32 + 8 + g) * 72 + k8);
            uint2 A2 = *(const uint2*)(Ds + (wm * 32 + 16 + g) * 72 + k8);
            uint2 A3 = *(const uint2*)(Ds + (wm * 32 + 24 + g) * 72 + k8);
            #pragma unroll
            for (int nt = 0; nt < 2; nt++) {
                uint2 Bv = *(const uint2*)(DF + (wn * 16 + nt * 8 + g) * 72 + k8);
                mma8(df[0][nt], A0.x, A1.x, A0.y, A1.y, Bv.x, Bv.y);
                mma8(df[1][nt], A2.x, A3.x, A2.y, A3.y, Bv.x, Bv.y);
            }
        }
        // P = (cf+bc)*(df+128*bd) -> Pb (packed tf32)
        int hc = c * 64;
        #pragma unroll
        for (int mt = 0; mt < 2; mt++)
        #pragma unroll
        for (int nt = 0; nt < 2; nt++) {
            int o = wn * 16 + nt * 8;
            int col = o + 2 * t;
            int row = wm * 32 + mt * 16 + g;
            float b0c = bc[hc + col], b1c = bc[hc + col + 1];
            float b0d = bd[hc + col], b1d = bd[hc + col + 1];
            float* f4 = cf[mt][nt];
            float* d4 = df[mt][nt];
            int a0 = row * 72 + o + pe;
            int a1 = (row + 8) * 72 + o + pe;
            Pu[a0]     = f2tf((f4[0] + b0c) * (d4[0] + b0d));
            Pu[a0 + 2] = f2tf((f4[1] + b1c) * (d4[1] + b1d));
            Pu[a1]     = f2tf((f4[2] + b0c) * (d4[2] + b0d));
            Pu[a1 + 2] = f2tf((f4[3] + b1c) * (d4[3] + b1d));
        }

        __syncthreads();   // sync B: Pb + FCb ready

        // fc: Pb[64x64] @ FCb^T accumulate (warp tile 32x32)
        #pragma unroll
        for (int ks = 0; ks < 8; ks++) {
            int k8 = ks * 8 + 2 * t;
            uint2 A0 = *(const uint2*)(Pb + (wm * 32 + g) * 72 + k8);
            uint2 A1 = *(const uint2*)(Pb + (wm * 32 + 8 + g) * 72 + k8);
            uint2 A2 = *(const uint2*)(Pb + (wm * 32 + 16 + g) * 72 + k8);
            uint2 A3 = *(const uint2*)(Pb + (wm * 32 + 24 + g) * 72 + k8);
            #pragma unroll
            for (int nt = 0; nt < 4; nt++) {
                uint2 Bv = *(const uint2*)(FCb + (wn * 32 + nt * 8 + g) * 72 + k8);
                mma8(hacc[0][nt], A0.x, A1.x, A0.y, A1.y, Bv.x, Bv.y);
                mma8(hacc[1][nt], A2.x, A3.x, A2.y, A3.y, Bv.x, Bv.y);
            }
        }

        if (c == 3) {
            if (l < 2) {
                // x = h + tanh(h) -> Xs (packed); next layer biases
                #pragma unroll
                for (int mt = 0; mt < 2; mt++)
                #pragma unroll
                for (int nt = 0; nt < 4; nt++) {
                    int o = wn * 32 + nt * 8;
                    int row = wm * 32 + mt * 16 + g;
                    float* h4 = hacc[mt][nt];
                    int a0 = row * 136 + o + pe;
                    int a1 = (row + 8) * 136 + o + pe;
                    Xu[a0]     = f2tf(h4[0] + tanh_fast(h4[0]));
                    Xu[a0 + 2] = f2tf(h4[1] + tanh_fast(h4[1]));
                    Xu[a1]     = f2tf(h4[2] + tanh_fast(h4[2]));
                    Xu[a1 + 2] = f2tf(h4[3] + tanh_fast(h4[3]));
                }
                bc[tid] = Wcf_b[(l + 1) * H_ + tid];
                bd[tid] = 128.f * Wdf_b[(l + 1) * H_ + tid];
                #pragma unroll
                for (int mt = 0; mt < 2; mt++)
                #pragma unroll
                for (int nt = 0; nt < 4; nt++)
                #pragma unroll
                for (int e = 0; e < 4; e++) hacc[mt][nt][e] = 0.f;
            } else {
                #pragma unroll
                for (int mt = 0; mt < 2; mt++)
                #pragma unroll
                for (int nt = 0; nt < 4; nt++) {
                    int col = wn * 32 + nt * 8 + 2 * t;
                    float* h4 = hacc[mt][nt];
                    pool += (h4[0] + tanh_fast(h4[0])) * vv[col];
                    pool += (h4[1] + tanh_fast(h4[1])) * vv[col + 1];
                    pool += (h4[2] + tanh_fast(h4[2])) * vv[col];
                    pool += (h4[3] + tanh_fast(h4[3])) * vv[col + 1];
                }
                rd[tid] = pool;
                __syncthreads();
                for (int s = 128; s > 0; s >>= 1) {
                    if (tid < s) rd[tid] += rd[tid + s];
                    __syncthreads();
                }
                if (tid == 0) atomicAdd(out + (blockIdx.x >> 1), rd[0]);
            }
        }
    }
}

// ---------------- launch ----------------
extern "C" void kernel_launch(void* const* d_in, const int* in_sizes, int n_in,
                              void* d_out, int out_size) {
    const float* x     = (const float*)d_in[0];
    const float* dist  = (const float*)d_in[1];
    const float* Wcf_w = (const float*)d_in[2];
    const float* Wcf_b = (const float*)d_in[3];
    const float* Wdf_w = (const float*)d_in[4];
    const float* Wdf_b = (const float*)d_in[5];
    const float* Wfc_w = (const float*)d_in[6];
    const float* fc0_w = (const float*)d_in[7];
    const float* fc0_b = (const float*)d_in[8];
    const float* out_w = (const float*)d_in[9];
    const float* out_b = (const float*)d_in[10];
    float* out = (float*)d_out;

    cudaFuncSetAttribute(dtnn_mma_kernel,
                         cudaFuncAttributeMaxDynamicSharedMemorySize, SMEMB);

    reduce_dist_kernel<<<ROWS, 256>>>(dist);
    fold_head_kernel<<<1, 128>>>(fc0_w, fc0_b, out_w, out_b, out);
    dtnn_mma_kernel<<<128, 256, SMEMB>>>(x, Wcf_w, Wcf_b, Wdf_w, Wdf_b, Wfc_w, out);
}

// round 7
// speedup vs baseline: 1.4384x; 1.3404x over previous
#include <cuda_runtime.h>
#include <cstdint>

#define B_   64
#define N_   128
#define F_   128
#define R_   64
#define H_   256
#define L_   3
#define ROWS (B_*N_)

// image sizes in words
#define CFW 8704    // [64][136]
#define DFW 4608    // [64][72]
#define FCW 9216    // [128][72]
#define XSW 8704    // [64][136]
#define DSW 4608    // [64][72]

__device__ float4 g_cf[12 * CFW / 4];
__device__ float4 g_df[12 * DFW / 4];
__device__ float4 g_fc[12 * FCW / 4];
__device__ float4 g_xs[128 * XSW / 4];
__device__ float4 g_ds[128 * DSW / 4];
__device__ float g_v[F_];

__device__ __forceinline__ uint32_t f2tf(float x) {
    uint32_t r; asm("cvt.rna.tf32.f32 %0, %1;" : "=r"(r) : "f"(x)); return r;
}
__device__ __forceinline__ float tanh_fast(float x) {
    float r; asm("tanh.approx.f32 %0, %1;" : "=f"(r) : "f"(x)); return r;
}
__device__ __forceinline__ int pk(int k) {           // packed octet permutation
    return (k & ~7) + 2 * (k & 3) + ((k >> 2) & 1);
}
__device__ __forceinline__ void mma8(float* d, uint32_t a0, uint32_t a1, uint32_t a2, uint32_t a3,
                                     uint32_t b0, uint32_t b1) {
    asm volatile(
        "mma.sync.aligned.m16n8k8.row.col.f32.tf32.tf32.f32 "
        "{%0,%1,%2,%3},{%4,%5,%6,%7},{%8,%9},{%0,%1,%2,%3};"
        : "+f"(d[0]), "+f"(d[1]), "+f"(d[2]), "+f"(d[3])
        : "r"(a0), "r"(a1), "r"(a2), "r"(a3), "r"(b0), "r"(b1));
}
__device__ __forceinline__ void cpa16(uint32_t dst, const float4* src) {
    asm volatile("cp.async.ca.shared.global [%0], [%1], 16;" :: "r"(dst), "l"(src));
}
#define CP_COMMIT() asm volatile("cp.async.commit_group;" ::: "memory")
template<int N>
__device__ __forceinline__ void cp_wait() {
    asm volatile("cp.async.wait_group %0;" :: "n"(N) : "memory");
}
template<int NC>
__device__ __forceinline__ void copy_img(uint32_t dst, const float4* __restrict__ src, int tid) {
    #pragma unroll
    for (int i = tid; i < NC; i += 256) cpa16(dst + i * 16, src + i);
}
__device__ __forceinline__ uint32_t smem_u32(const void* p) {
    uint32_t a;
    asm("{ .reg .u64 t; cvta.to.shared.u64 t, %1; cvt.u32.u64 %0, t; }" : "=r"(a) : "l"(p));
    return a;
}

// ---------------- Kernel 0: prep — pack weights/x to tf32 smem-images; fold head ----------------
__global__ void prep_kernel(const float* __restrict__ x,
                            const float* __restrict__ Wcf_w, const float* __restrict__ Wdf_w,
                            const float* __restrict__ Wfc_w,
                            const float* __restrict__ fc0_w, const float* __restrict__ fc0_b,
                            const float* __restrict__ out_w, const float* __restrict__ out_b,
                            float* __restrict__ out) {
    int bid = blockIdx.x, tid = threadIdx.x;
    if (bid < 128) {                       // x tile images
        float* dst = (float*)g_xs + bid * XSW;
        const float* src = x + (size_t)bid * 64 * 128;
        for (int idx = tid; idx < 64 * 128; idx += 256) {
            int row = idx >> 7, k = idx & 127;
            dst[row * 136 + pk(k)] = __uint_as_float(f2tf(src[idx]));
        }
    } else if (bid < 140) {                // weight chunk images
        int wi = bid - 128, l = wi >> 2, c = wi & 3;
        float* dcf = (float*)g_cf + wi * CFW;
        const float* scf = Wcf_w + (size_t)l * 32768 + c * 64 * 128;
        for (int idx = tid; idx < 64 * 128; idx += 256) {
            int row = idx >> 7, k = idx & 127;
            dcf[row * 136 + pk(k)] = __uint_as_float(f2tf(scf[idx]));
        }
        float* ddf = (float*)g_df + wi * DFW;
        const float* sdf = Wdf_w + (size_t)l * 16384 + c * 64 * 64;
        for (int idx = tid; idx < 64 * 64; idx += 256) {
            int row = idx >> 6, k = idx & 63;
            ddf[row * 72 + pk(k)] = __uint_as_float(f2tf(sdf[idx]));
        }
        float* dfc = (float*)g_fc + wi * FCW;
        const float* sfc = Wfc_w + (size_t)l * 32768 + c * 64;
        for (int idx = tid; idx < 128 * 64; idx += 256) {
            int row = idx >> 6, k = idx & 63;
            dfc[row * 72 + pk(k)] = __uint_as_float(f2tf(sfc[row * 256 + k]));
        }
    } else {                               // fold head + init out
        if (tid < 128) {
            float a = 0.f;
            #pragma unroll 8
            for (int c = 0; c < 256; c++) a += out_w[c] * fc0_w[c * F_ + tid];
            g_v[tid] = a;
        }
        __shared__ float cs;
        if (tid == 0) {
            float s = out_b[0];
            for (int c = 0; c < 256; c++) s += out_w[c] * fc0_b[c];
            cs = s;
        }
        __syncthreads();
        if (tid < B_) out[tid] = cs;
    }
}

// ---------------- Kernel A: d_sum row reduction -> packed Ds images ----------------
__global__ void reduce_dist_kernel(const float* __restrict__ dist) {
    int row = blockIdx.x;
    int tid = threadIdx.x;
    const float4* p = (const float4*)(dist + (size_t)row * (N_ * R_));
    float4 acc = make_float4(0.f, 0.f, 0.f, 0.f);
    #pragma unroll
    for (int t = 0; t < 8; t++) {
        float4 v = __ldcs(&p[tid + t * 256]);
        acc.x += v.x; acc.y += v.y; acc.z += v.z; acc.w += v.w;
    }
    __shared__ float4 s[256];
    s[tid] = acc;
    __syncthreads();
    if (tid < 16) {
        float4 a = s[tid];
        #pragma unroll
        for (int m = 1; m < 16; m++) {
            float4 b = s[tid + 16 * m];
            a.x += b.x; a.y += b.y; a.z += b.z; a.w += b.w;
        }
        int c4 = tid * 4;
        float* dp = (float*)g_ds + (row >> 6) * DSW + (row & 63) * 72
                    + (c4 & ~7) + ((c4 & 4) ? 1 : 0);
        dp[0] = __uint_as_float(f2tf(a.x));
        dp[2] = __uint_as_float(f2tf(a.y));
        dp[4] = __uint_as_float(f2tf(a.z));
        dp[6] = __uint_as_float(f2tf(a.w));
    }
}

// ---------------- Kernel B: mma.sync tf32 fused 3 layers + pooling ----------------
// 128 CTAs x 64 rows, 256 threads. smem word offsets:
enum {
    OXS  = 0,                    // Xs  [64][136]
    ODS  = OXS + XSW,            // Ds  [64][72]
    OPB  = ODS + DSW,            // Pb  [64][72]
    OCF0 = OPB + 4608,
    OCF1 = OCF0 + CFW,
    ODF0 = OCF1 + CFW,
    ODF1 = ODF0 + DFW,
    OFC  = ODF1 + DFW,
    OBC  = OFC + FCW,            // bcf [256]
    OBD  = OBC + 256,            // 128*bdf [256]
    OVV  = OBD + 256,            // v [128]
    ORD  = OVV + 128,            // reduce [256]
    TOTW = ORD + 256
};
#define SMEMB (TOTW * 4)

__global__ __launch_bounds__(256, 1)
void dtnn_mma_kernel(const float* __restrict__ Wcf_b, const float* __restrict__ Wdf_b,
                     float* __restrict__ out) {
    extern __shared__ float sm[];
    float* Xs = sm + OXS; float* Ds = sm + ODS; float* Pb = sm + OPB;
    float* CFs[2] = { sm + OCF0, sm + OCF1 };
    float* DFs[2] = { sm + ODF0, sm + ODF1 };
    float* FCb = sm + OFC;
    float* bc = sm + OBC; float* bd = sm + OBD;
    float* vv = sm + OVV; float* rd = sm + ORD;
    uint32_t sb = smem_u32(sm);
    uint32_t* Xu = (uint32_t*)Xs;
    uint32_t* Pu = (uint32_t*)Pb;

    int tid = threadIdx.x, lane = tid & 31, w = tid >> 5;
    int g = lane >> 2, t = lane & 3;
    int wm = w & 1, wn = w >> 1;          // warp grid: 2 (M) x 4 (N)
    int pe = (t < 2) ? 4 * t : 4 * t - 7; // packed pos of even col 2t; odd at +2
    int bid = blockIdx.x;

    // pre-loop async loads: Xs, Ds, CF[0], DF[0]
    copy_img<XSW/4>(sb + OXS * 4, g_xs + bid * (XSW/4), tid);
    copy_img<DSW/4>(sb + ODS * 4, g_ds + bid * (DSW/4), tid);
    copy_img<CFW/4>(sb + OCF0 * 4, g_cf, tid);
    copy_img<DFW/4>(sb + ODF0 * 4, g_df, tid);
    CP_COMMIT();
    bc[tid] = Wcf_b[tid];
    bd[tid] = 128.f * Wdf_b[tid];
    if (tid < 128) vv[tid] = g_v[tid];
    cp_wait<0>();
    __syncthreads();

    float hacc[2][4][4] = {};
    float pool = 0.f;

    for (int i = 0; i < 12; i++) {
        int l = i >> 2, c = i & 3, buf = i & 1;

        // issue FC[i]; then CF/DF[i+1] into alternate buffers
        copy_img<FCW/4>(sb + OFC * 4, g_fc + i * (FCW/4), tid);
        CP_COMMIT();
        if (i < 11) {
            uint32_t cfo = (buf ? OCF0 : OCF1) * 4;
            uint32_t dfo = (buf ? ODF0 : ODF1) * 4;
            copy_img<CFW/4>(sb + cfo, g_cf + (i + 1) * (CFW/4), tid);
            copy_img<DFW/4>(sb + dfo, g_df + (i + 1) * (DFW/4), tid);
            CP_COMMIT();
        }

        float* CF = CFs[buf];
        float* DF = DFs[buf];
        float cf[2][2][4] = {}, df[2][2][4] = {};
        // cf: Xs[64x128] @ CF^T (warp tile 32x16)
        #pragma unroll
        for (int ks = 0; ks < 16; ks++) {
            int k8 = ks * 8 + 2 * t;
            uint2 A0 = *(const uint2*)(Xs + (wm * 32 + g) * 136 + k8);
            uint2 A1 = *(const uint2*)(Xs + (wm * 32 + 8 + g) * 136 + k8);
            uint2 A2 = *(const uint2*)(Xs + (wm * 32 + 16 + g) * 136 + k8);
            uint2 A3 = *(const uint2*)(Xs + (wm * 32 + 24 + g) * 136 + k8);
            #pragma unroll
            for (int nt = 0; nt < 2; nt++) {
                uint2 Bv = *(const uint2*)(CF + (wn * 16 + nt * 8 + g) * 136 + k8);
                mma8(cf[0][nt], A0.x, A1.x, A0.y, A1.y, Bv.x, Bv.y);
                mma8(cf[1][nt], A2.x, A3.x, A2.y, A3.y, Bv.x, Bv.y);
            }
        }
        // df: Ds[64x64] @ DF^T
        #pragma unroll
        for (int ks = 0; ks < 8; ks++) {
            int k8 = ks * 8 + 2 * t;
            uint2 A0 = *(const uint2*)(Ds + (wm * 32 + g) * 72 + k8);
            uint2 A1 = *(const uint2*)(Ds + (wm * 32 + 8 + g) * 72 + k8);
            uint2 A2 = *(const uint2*)(Ds + (wm * 32 + 16 + g) * 72 + k8);
            uint2 A3 = *(const uint2*)(Ds + (wm * 32 + 24 + g) * 72 + k8);
            #pragma unroll
            for (int nt = 0; nt < 2; nt++) {
                uint2 Bv = *(const uint2*)(DF + (wn * 16 + nt * 8 + g) * 72 + k8);
                mma8(df[0][nt], A0.x, A1.x, A0.y, A1.y, Bv.x, Bv.y);
                mma8(df[1][nt], A2.x, A3.x, A2.y, A3.y, Bv.x, Bv.y);
            }
        }
        // P = (cf+bc)*(df+128*bd) -> Pb (packed tf32)
        int hc = c * 64;
        #pragma unroll
        for (int mt = 0; mt < 2; mt++)
        #pragma unroll
        for (int nt = 0; nt < 2; nt++) {
            int o = wn * 16 + nt * 8;
            int col = o + 2 * t;
            int row = wm * 32 + mt * 16 + g;
            float b0c = bc[hc + col], b1c = bc[hc + col + 1];
            float b0d = bd[hc + col], b1d = bd[hc + col + 1];
            float* f4 = cf[mt][nt];
            float* d4 = df[mt][nt];
            int a0 = row * 72 + o + pe;
            int a1 = (row + 8) * 72 + o + pe;
            Pu[a0]     = f2tf((f4[0] + b0c) * (d4[0] + b0d));
            Pu[a0 + 2] = f2tf((f4[1] + b1c) * (d4[1] + b1d));
            Pu[a1]     = f2tf((f4[2] + b0c) * (d4[2] + b0d));
            Pu[a1 + 2] = f2tf((f4[3] + b1c) * (d4[3] + b1d));
        }

        if (i < 11) cp_wait<1>(); else cp_wait<0>();   // FC[i] arrived
        __syncthreads();                                // Pb + FCb ready

        // fc: Pb[64x64] @ FCb^T accumulate (warp tile 32x32)
        #pragma unroll
        for (int ks = 0; ks < 8; ks++) {
            int k8 = ks * 8 + 2 * t;
            uint2 A0 = *(const uint2*)(Pb + (wm * 32 + g) * 72 + k8);
            uint2 A1 = *(const uint2*)(Pb + (wm * 32 + 8 + g) * 72 + k8);
            uint2 A2 = *(const uint2*)(Pb + (wm * 32 + 16 + g) * 72 + k8);
            uint2 A3 = *(const uint2*)(Pb + (wm * 32 + 24 + g) * 72 + k8);
            #pragma unroll
            for (int nt = 0; nt < 4; nt++) {
                uint2 Bv = *(const uint2*)(FCb + (wn * 32 + nt * 8 + g) * 72 + k8);
                mma8(hacc[0][nt], A0.x, A1.x, A0.y, A1.y, Bv.x, Bv.y);
                mma8(hacc[1][nt], A2.x, A3.x, A2.y, A3.y, Bv.x, Bv.y);
            }
        }

        if (c == 3) {
            if (l < 2) {
                // x = h + tanh(h) -> Xs (packed); next layer biases
                #pragma unroll
                for (int mt = 0; mt < 2; mt++)
                #pragma unroll
                for (int nt = 0; nt < 4; nt++) {
                    int o = wn * 32 + nt * 8;
                    int row = wm * 32 + mt * 16 + g;
                    float* h4 = hacc[mt][nt];
                    int a0 = row * 136 + o + pe;
                    int a1 = (row + 8) * 136 + o + pe;
                    Xu[a0]     = f2tf(h4[0] + tanh_fast(h4[0]));
                    Xu[a0 + 2] = f2tf(h4[1] + tanh_fast(h4[1]));
                    Xu[a1]     = f2tf(h4[2] + tanh_fast(h4[2]));
                    Xu[a1 + 2] = f2tf(h4[3] + tanh_fast(h4[3]));
                }
                bc[tid] = Wcf_b[(l + 1) * H_ + tid];
                bd[tid] = 128.f * Wdf_b[(l + 1) * H_ + tid];
                #pragma unroll
                for (int mt = 0; mt < 2; mt++)
                #pragma unroll
                for (int nt = 0; nt < 4; nt++)
                #pragma unroll
                for (int e = 0; e < 4; e++) hacc[mt][nt][e] = 0.f;
            } else {
                #pragma unroll
                for (int mt = 0; mt < 2; mt++)
                #pragma unroll
                for (int nt = 0; nt < 4; nt++) {
                    int col = wn * 32 + nt * 8 + 2 * t;
                    float* h4 = hacc[mt][nt];
                    pool += (h4[0] + tanh_fast(h4[0])) * vv[col];
                    pool += (h4[1] + tanh_fast(h4[1])) * vv[col + 1];
                    pool += (h4[2] + tanh_fast(h4[2])) * vv[col];
                    pool += (h4[3] + tanh_fast(h4[3])) * vv[col + 1];
                }
                rd[tid] = pool;
                __syncthreads();
                for (int s = 128; s > 0; s >>= 1) {
                    if (tid < s) rd[tid] += rd[tid + s];
                    __syncthreads();
                }
                if (tid == 0) atomicAdd(out + (blockIdx.x >> 1), rd[0]);
            }
        }
        if (i < 11) { __syncthreads(); }   // ensure CF/DF[i+1] wait point is collective
    }
}

// ---------------- launch ----------------
extern "C" void kernel_launch(void* const* d_in, const int* in_sizes, int n_in,
                              void* d_out, int out_size) {
    const float* x     = (const float*)d_in[0];
    const float* dist  = (const float*)d_in[1];
    const float* Wcf_w = (const float*)d_in[2];
    const float* Wcf_b = (const float*)d_in[3];
    const float* Wdf_w = (const float*)d_in[4];
    const float* Wdf_b = (const float*)d_in[5];
    const float* Wfc_w = (const float*)d_in[6];
    const float* fc0_w = (const float*)d_in[7];
    const float* fc0_b = (const float*)d_in[8];
    const float* out_w = (const float*)d_in[9];
    const float* out_b = (const float*)d_in[10];
    float* out = (float*)d_out;

    cudaFuncSetAttribute(dtnn_mma_kernel,
                         cudaFuncAttributeMaxDynamicSharedMemorySize, SMEMB);

    prep_kernel<<<141, 256>>>(x, Wcf_w, Wdf_w, Wfc_w, fc0_w, fc0_b, out_w, out_b, out);
    reduce_dist_kernel<<<ROWS, 256>>>(dist);
    dtnn_mma_kernel<<<128, 256, SMEMB>>>(Wcf_b, Wdf_b, out);
}